// round 17
// baseline (speedup 1.0000x reference)
#include <cuda_runtime.h>
#include <cuda_fp16.h>

// Fixed shapes for SPHERE_CUDA_77163382440039
static constexpr int HW  = 512 * 512;   // 262144 HT cells
static constexpr int NCH = 128;         // flat channels (B4 * C4)
static constexpr int S   = 32768;       // sphere bins
static constexpr int CAP = 128;         // bucket capacity per bin (Poisson(45.8))

// Scratch (static __device__ — no runtime allocation).
// g_cursor is zero-initialized at module load; accum_kernel's cursor READ is
// a destructive atomicExch(...,0), so every kernel_launch (first call and
// every graph replay) starts from all-zero cursors with no zero kernel.
__device__ __align__(16) __half g_xTh[(size_t)HW * NCH];     // x transposed [hw][ch], fp16, 67 MB
__device__ __align__(16) float2 g_bucket[(size_t)S * CAP];   // (h bits, weight) per bin, 33.5 MB
__device__ __align__(16) int g_cursor[S];

// ---------------------------------------------------------------------------
// FUSED + PIPELINED: transpose+convert (x [128][HW] fp32 -> g_xTh [HW][128]
// fp16) AND vote scatter. Each block processes 4 tiles with double-buffered
// smem: cp.async loads for tile j+1 are in flight while tile j is converted
// and stored; vote-scatter chunks run in the latency shadow each iteration.
// Grid: 2048 blocks; block b handles tiles b, b+2048, b+4096, b+6144
// (same hw range, 4 channel groups).
__global__ __launch_bounds__(256) void fused_transpose_scatter_kernel(
    const float* __restrict__ in,
    const int* __restrict__ ht_idx,
    const int* __restrict__ sp_idx,
    const float* __restrict__ weight,
    int nvotes) {
    __shared__ float4 tile4[2][32][32];     // 2 x 16 KB, [ch][swizzled hw4]
    const int t   = threadIdx.x;
    const int hw4 = t & 31;
    const int c0  = t >> 5;
    const int h0  = blockIdx.x * 128;       // hw base (same for all 4 tiles)

    unsigned long long pol;
    asm volatile("createpolicy.fractional.L2::evict_first.b64 %0, 1.0;"
                 : "=l"(pol));

    // Issue loads for tile 0 into buffer 0.
    #pragma unroll
    for (int k = 0; k < 4; k++) {
        int ch_l = c0 + k * 8;
        unsigned dst = (unsigned)__cvta_generic_to_shared(&tile4[0][0][0]) +
            (unsigned)((ch_l * 32 + (hw4 ^ (((ch_l >> 3) & 3) << 1))) * 16);
        const float* src = &in[(size_t)ch_l * HW + h0 + hw4 * 4];
        asm volatile(
            "cp.async.cg.shared.global.L2::cache_hint [%0], [%1], 16, %2;"
            :: "r"(dst), "l"(src), "l"(pol) : "memory");
    }
    asm volatile("cp.async.commit_group;");

    #pragma unroll
    for (int j = 0; j < 4; j++) {
        // Issue loads for tile j+1 into the other buffer.
        if (j + 1 < 4) {
            int r0n = (j + 1) * 32;
            #pragma unroll
            for (int k = 0; k < 4; k++) {
                int ch_l = c0 + k * 8;
                unsigned dst = (unsigned)__cvta_generic_to_shared(
                        &tile4[(j + 1) & 1][0][0]) +
                    (unsigned)((ch_l * 32 +
                        (hw4 ^ (((ch_l >> 3) & 3) << 1))) * 16);
                const float* src = &in[(size_t)(r0n + ch_l) * HW + h0 + hw4 * 4];
                asm volatile(
                    "cp.async.cg.shared.global.L2::cache_hint [%0], [%1], 16, %2;"
                    :: "r"(dst), "l"(src), "l"(pol) : "memory");
            }
            asm volatile("cp.async.commit_group;");
        }

        // Scatter one vote chunk in the latency shadow.
        {
            int v = (blockIdx.x * 4 + j) * 256 + t;
            if (v < nvotes) {
                int s    = __ldcs(&sp_idx[v]);
                int h    = __ldcs(&ht_idx[v]);
                float wv = __ldcs(&weight[v]);
                int pos = atomicAdd(&g_cursor[s], 1);
                if (pos < CAP) {
                    g_bucket[(size_t)s * CAP + pos] =
                        make_float2(__int_as_float(h), wv);
                }
            }
        }

        // Wait for tile j's data (leave tile j+1's group pending).
        if (j + 1 < 4) {
            asm volatile("cp.async.wait_group 1;" ::: "memory");
        } else {
            asm volatile("cp.async.wait_group 0;" ::: "memory");
        }
        __syncthreads();

        // Phase 2: conflict-free scalar smem reads -> pack 8 halves ->
        // 16B global stores in 64B full-sector runs.
        {
            const float* tf = reinterpret_cast<const float*>(&tile4[j & 1][0][0]);
            const int r0 = j * 32;
            #pragma unroll
            for (int k = 0; k < 2; k++) {
                int chg  = t & 3;
                int hw_l = (t >> 5) * 8 + ((t & 31) >> 2) + k * 64;
                int swz  = (chg << 1);
                int col  = ((hw_l >> 2) ^ swz) * 4 + (hw_l & 3);
                float f0 = tf[(chg * 8 + 0) * 128 + col];
                float f1 = tf[(chg * 8 + 1) * 128 + col];
                float f2 = tf[(chg * 8 + 2) * 128 + col];
                float f3 = tf[(chg * 8 + 3) * 128 + col];
                float f4 = tf[(chg * 8 + 4) * 128 + col];
                float f5 = tf[(chg * 8 + 5) * 128 + col];
                float f6 = tf[(chg * 8 + 6) * 128 + col];
                float f7 = tf[(chg * 8 + 7) * 128 + col];
                __half2 h0p = __floats2half2_rn(f0, f1);
                __half2 h1p = __floats2half2_rn(f2, f3);
                __half2 h2p = __floats2half2_rn(f4, f5);
                __half2 h3p = __floats2half2_rn(f6, f7);
                uint4 pk;
                pk.x = *reinterpret_cast<const unsigned*>(&h0p);
                pk.y = *reinterpret_cast<const unsigned*>(&h1p);
                pk.z = *reinterpret_cast<const unsigned*>(&h2p);
                pk.w = *reinterpret_cast<const unsigned*>(&h3p);
                *reinterpret_cast<uint4*>(
                    &g_xTh[(size_t)(h0 + hw_l) * NCH + r0 + chg * 8]) = pk;
            }
        }
        // Buffer j&1 is reused for tile j+2's loads next iteration.
        __syncthreads();
    }
}

// ---------------------------------------------------------------------------
// One warp per sphere bin; lane l owns channels [4l, 4l+4) in fp32 registers.
// R16-proven (byte-identical): destructive atomicExch cursor read, cp.async
// record staging into smem, unroll-8 gather loop, smem-staged fused output
// transpose.
__global__ __launch_bounds__(256) void accum_kernel(float* __restrict__ out) {
    __shared__ __align__(16) float2 srec[8][CAP];   // 8 KB record staging
    const int warp = threadIdx.x >> 5;
    const int lane = threadIdx.x & 31;
    const int s    = blockIdx.x * 8 + warp;

    int n = 0;
    if (lane == 0) n = atomicExch(&g_cursor[s], 0);
    n = __shfl_sync(0xffffffffu, n, 0);
    if (n > CAP) n = CAP;
    const float2* __restrict__ grec = &g_bucket[(size_t)s * CAP];

    // Prefetch used records (16B granules = 2 records each) via cp.async.
    {
        int gcnt = (n + 1) >> 1;    // float4 granules needed (<= 64)
        unsigned sbase = (unsigned)__cvta_generic_to_shared(&srec[warp][0]);
        if (lane < gcnt) {
            asm volatile("cp.async.ca.shared.global [%0], [%1], 16;"
                         :: "r"(sbase + lane * 16),
                            "l"(reinterpret_cast<const float4*>(grec) + lane)
                         : "memory");
        }
        if (lane + 32 < gcnt) {
            asm volatile("cp.async.ca.shared.global [%0], [%1], 16;"
                         :: "r"(sbase + (lane + 32) * 16),
                            "l"(reinterpret_cast<const float4*>(grec) + lane + 32)
                         : "memory");
        }
        asm volatile("cp.async.commit_group;");
        asm volatile("cp.async.wait_group 0;" ::: "memory");
        __syncwarp();
    }

    const float2* __restrict__ rec  = &srec[warp][0];
    const float4* __restrict__ rec4 = reinterpret_cast<const float4*>(rec);
    const size_t col = (size_t)(lane * 4);

    float4 a0 = make_float4(0.f, 0.f, 0.f, 0.f);
    float4 a1 = make_float4(0.f, 0.f, 0.f, 0.f);

    int i = 0;
    for (; i + 8 <= n; i += 8) {
        float4 ra = rec4[(i >> 1) + 0];
        float4 rb = rec4[(i >> 1) + 1];
        float4 rc = rec4[(i >> 1) + 2];
        float4 rd = rec4[(i >> 1) + 3];
        const uint2 p0 = *reinterpret_cast<const uint2*>(
            &g_xTh[(size_t)__float_as_int(ra.x) * NCH + col]);
        const uint2 p1 = *reinterpret_cast<const uint2*>(
            &g_xTh[(size_t)__float_as_int(ra.z) * NCH + col]);
        const uint2 p2 = *reinterpret_cast<const uint2*>(
            &g_xTh[(size_t)__float_as_int(rb.x) * NCH + col]);
        const uint2 p3 = *reinterpret_cast<const uint2*>(
            &g_xTh[(size_t)__float_as_int(rb.z) * NCH + col]);
        const uint2 p4 = *reinterpret_cast<const uint2*>(
            &g_xTh[(size_t)__float_as_int(rc.x) * NCH + col]);
        const uint2 p5 = *reinterpret_cast<const uint2*>(
            &g_xTh[(size_t)__float_as_int(rc.z) * NCH + col]);
        const uint2 p6 = *reinterpret_cast<const uint2*>(
            &g_xTh[(size_t)__float_as_int(rd.x) * NCH + col]);
        const uint2 p7 = *reinterpret_cast<const uint2*>(
            &g_xTh[(size_t)__float_as_int(rd.z) * NCH + col]);

        float2 f;
        f = __half22float2(*reinterpret_cast<const __half2*>(&p0.x));
        a0.x += f.x * ra.y; a0.y += f.y * ra.y;
        f = __half22float2(*reinterpret_cast<const __half2*>(&p0.y));
        a0.z += f.x * ra.y; a0.w += f.y * ra.y;
        f = __half22float2(*reinterpret_cast<const __half2*>(&p1.x));
        a1.x += f.x * ra.w; a1.y += f.y * ra.w;
        f = __half22float2(*reinterpret_cast<const __half2*>(&p1.y));
        a1.z += f.x * ra.w; a1.w += f.y * ra.w;

        f = __half22float2(*reinterpret_cast<const __half2*>(&p2.x));
        a0.x += f.x * rb.y; a0.y += f.y * rb.y;
        f = __half22float2(*reinterpret_cast<const __half2*>(&p2.y));
        a0.z += f.x * rb.y; a0.w += f.y * rb.y;
        f = __half22float2(*reinterpret_cast<const __half2*>(&p3.x));
        a1.x += f.x * rb.w; a1.y += f.y * rb.w;
        f = __half22float2(*reinterpret_cast<const __half2*>(&p3.y));
        a1.z += f.x * rb.w; a1.w += f.y * rb.w;

        f = __half22float2(*reinterpret_cast<const __half2*>(&p4.x));
        a0.x += f.x * rc.y; a0.y += f.y * rc.y;
        f = __half22float2(*reinterpret_cast<const __half2*>(&p4.y));
        a0.z += f.x * rc.y; a0.w += f.y * rc.y;
        f = __half22float2(*reinterpret_cast<const __half2*>(&p5.x));
        a1.x += f.x * rc.w; a1.y += f.y * rc.w;
        f = __half22float2(*reinterpret_cast<const __half2*>(&p5.y));
        a1.z += f.x * rc.w; a1.w += f.y * rc.w;

        f = __half22float2(*reinterpret_cast<const __half2*>(&p6.x));
        a0.x += f.x * rd.y; a0.y += f.y * rd.y;
        f = __half22float2(*reinterpret_cast<const __half2*>(&p6.y));
        a0.z += f.x * rd.y; a0.w += f.y * rd.y;
        f = __half22float2(*reinterpret_cast<const __half2*>(&p7.x));
        a1.x += f.x * rd.w; a1.y += f.y * rd.w;
        f = __half22float2(*reinterpret_cast<const __half2*>(&p7.y));
        a1.z += f.x * rd.w; a1.w += f.y * rd.w;
    }
    for (; i < n; i++) {
        float2 r0 = rec[i];
        const uint2 p0 = *reinterpret_cast<const uint2*>(
            &g_xTh[(size_t)__float_as_int(r0.x) * NCH + col]);
        float2 f;
        f = __half22float2(*reinterpret_cast<const __half2*>(&p0.x));
        a0.x += f.x * r0.y; a0.y += f.y * r0.y;
        f = __half22float2(*reinterpret_cast<const __half2*>(&p0.y));
        a0.z += f.x * r0.y; a0.w += f.y * r0.y;
    }
    a0.x += a1.x; a0.y += a1.y; a0.z += a1.z; a0.w += a1.w;

    // Stage [8 bins][128 ch] in smem, then write out[ch][s0..s0+7] coalesced.
    __shared__ float sm[8][128];
    *reinterpret_cast<float4*>(&sm[warp][lane * 4]) = a0;
    __syncthreads();

    if (threadIdx.x < 128) {
        const int ch = threadIdx.x;
        const int s0 = blockIdx.x * 8;
        float4 o0 = make_float4(sm[0][ch], sm[1][ch], sm[2][ch], sm[3][ch]);
        float4 o1 = make_float4(sm[4][ch], sm[5][ch], sm[6][ch], sm[7][ch]);
        float4* dst = reinterpret_cast<float4*>(&out[(size_t)ch * S + s0]);
        dst[0] = o0;
        dst[1] = o1;
    }
}

// ---------------------------------------------------------------------------
extern "C" void kernel_launch(void* const* d_in, const int* in_sizes, int n_in,
                              void* d_out, int out_size) {
    const float* x      = (const float*)d_in[0];  // [128][262144] flat
    const int*   ht     = (const int*)d_in[1];
    const int*   sp     = (const int*)d_in[2];
    const float* w      = (const float*)d_in[3];
    float*       out    = (float*)d_out;          // [128][32768] flat
    const int    nvotes = in_sizes[1];

    // 1) Fused + pipelined transpose/convert AND vote scatter (4 tiles per
    //    block, double-buffered cp.async). Cursors are guaranteed zero here:
    //    static init on first call, accum's atomicExch afterwards.
    fused_transpose_scatter_kernel<<<2048, 256>>>(x, ht, sp, w, nvotes);

    // 2) Per-bin register accumulation (R16-proven) + fused output transpose.
    accum_kernel<<<S / 8, 256>>>(out);
}